// round 1
// baseline (speedup 1.0000x reference)
#include <cuda_runtime.h>
#include <math.h>

#define BB 256
#define LL 256
#define DD 128
#define HH 2
#define EE 64
#define MROWS (BB*LL)     // 65536
#define KTOP 5
#define NTOT 100000

// ---------------- scratch (static device globals; no allocation) ----------------
static __device__ float g_x [MROWS*DD];
static __device__ float g_xf[MROWS*DD];
static __device__ float g_qt[MROWS*DD];
static __device__ float g_kt[MROWS*DD];
static __device__ float g_vt[MROWS*DD];
static __device__ float g_v [MROWS*DD];
static __device__ float g_ao[MROWS*DD];
static __device__ float g_a [MROWS*DD];
static __device__ float g_h [MROWS*2*DD];
static __device__ float g_sp[BB*HH*LL*EE];
static __device__ float g_S [BB*HH*LL*LL];   // 33.5M floats = 128MB
static __device__ float g_mv[BB*LL];
static __device__ int   g_delays[KTOP];
static __device__ float g_w[BB*KTOP];
static __device__ float g_hf[LL];

__device__ __forceinline__ float* bufsel(int s){
    switch(s){
        case 0: return g_x;  case 1: return g_xf; case 2: return g_qt;
        case 3: return g_kt; case 4: return g_vt; case 5: return g_v;
        case 6: return g_ao; case 7: return g_a;  default: return g_h;
    }
}

// ---------------- embedding: x = ego_emb[paths] + pos_emb ----------------
__global__ void embed_k(const int* __restrict__ paths,
                        const float* __restrict__ ego,
                        const float* __restrict__ pos){
    int bt = blockIdx.x; int t = bt & (LL-1); int d = threadIdx.x;
    int p = paths[bt];
    g_x[(size_t)bt*DD + d] = ego[(size_t)p*DD + d] + pos[t*DD + d];
}

// ---------------- band-pass impulse response h = irfft(mask) ----------------
__global__ void filt_k(int l, int r){
    int n = threadIdx.x;
    double s = 0.0;
    for (int f = l; f < r; f++){
        double w = (f == 0 || f == LL/2) ? 1.0 : 2.0;
        s += w * cos(6.283185307179586477 * (double)(f*n) / (double)LL);
    }
    g_hf[n] = (float)(s / (double)LL);
}

// ---------------- circulant filter along L:  Xf[b,t,:] = sum_s h[(t-s)%L] x[b,s,:] ----------------
__global__ void __launch_bounds__(256) circ_k(){
    __shared__ float hs[LL];
    __shared__ float xs[16][64];
    int b  = blockIdx.z;
    int t0 = blockIdx.x*64, d0 = blockIdx.y*64;
    int tid = threadIdx.x;
    hs[tid] = g_hf[tid];
    int ty = tid >> 4, tx = tid & 15;
    int lr = tid >> 4, lc = (tid & 15)*4;
    const float* Xb = g_x + (size_t)b*LL*DD;
    float acc[4][4] = {};
    for (int s0 = 0; s0 < LL; s0 += 16){
        *(float4*)&xs[lr][lc] = *(const float4*)&Xb[(size_t)(s0+lr)*DD + d0 + lc];
        __syncthreads();
        #pragma unroll
        for (int k = 0; k < 16; k++){
            int s = s0 + k;
            float a[4], bv[4];
            #pragma unroll
            for (int i=0;i<4;i++) a[i] = hs[(t0 + ty*4 + i - s) & (LL-1)];
            *(float4*)bv = *(float4*)&xs[k][tx*4];
            #pragma unroll
            for (int i=0;i<4;i++)
                #pragma unroll
                for (int j=0;j<4;j++)
                    acc[i][j] += a[i]*bv[j];
        }
        __syncthreads();
    }
    float* Yb = g_xf + (size_t)b*LL*DD;
    #pragma unroll
    for (int i=0;i<4;i++)
        #pragma unroll
        for (int j=0;j<4;j++)
            Yb[(size_t)(t0+ty*4+i)*DD + d0 + tx*4 + j] = acc[i][j];
}

// ---------------- generic GEMM: C(M,N) = act(A(M,K) @ W(K,N) [+ R]) ----------------
// act: 0 none, 1 residual add, 2 exact gelu
__global__ void __launch_bounds__(256) gemm_k(const float* __restrict__ Wmat,
        int asel, int csel, int rsel, int K, int N, int act){
    __shared__ float As[16][64];
    __shared__ float Bs[16][64];
    const float* A = bufsel(asel);
    float* C = bufsel(csel);
    const float* R = (rsel >= 0) ? bufsel(rsel) : (const float*)0;
    int bm = blockIdx.x*64, bn = blockIdx.y*64;
    int tid = threadIdx.x;
    int ty = tid>>4, tx = tid&15;
    int ar = tid>>2, ac = (tid&3)*4;
    int br = tid>>4, bc = (tid&15)*4;
    float acc[4][4] = {};
    for (int k0=0;k0<K;k0+=16){
        float4 av = *(const float4*)&A[(size_t)(bm+ar)*K + k0 + ac];
        As[ac+0][ar]=av.x; As[ac+1][ar]=av.y; As[ac+2][ar]=av.z; As[ac+3][ar]=av.w;
        *(float4*)&Bs[br][bc] = *(const float4*)&Wmat[(size_t)(k0+br)*N + bn + bc];
        __syncthreads();
        #pragma unroll
        for (int k=0;k<16;k++){
            float a[4], bv[4];
            *(float4*)a  = *(float4*)&As[k][ty*4];
            *(float4*)bv = *(float4*)&Bs[k][tx*4];
            #pragma unroll
            for (int i=0;i<4;i++)
                #pragma unroll
                for (int j=0;j<4;j++)
                    acc[i][j] += a[i]*bv[j];
        }
        __syncthreads();
    }
    #pragma unroll
    for (int i=0;i<4;i++){
        int r = bm + ty*4 + i;
        #pragma unroll
        for (int j=0;j<4;j++){
            int c = bn + tx*4 + j;
            float v = acc[i][j];
            if (act == 1) v += R[(size_t)r*N + c];
            else if (act == 2) v = 0.5f*v*(1.0f + erff(v*0.70710678118654752f));
            C[(size_t)r*N + c] = v;
        }
    }
}

// ---------------- S_h[b] = Qt_h @ Kt_h^T (per b,h, 256x256, K=64) ----------------
__global__ void __launch_bounds__(256) score_k(){
    __shared__ float Qs[16][64];
    __shared__ float Ks[16][64];
    int bh = blockIdx.z; int b = bh>>1, h = bh&1;
    int t0 = blockIdx.x*64, s0 = blockIdx.y*64;
    int tid = threadIdx.x;
    int ty = tid>>4, tx = tid&15;
    int ar = tid>>2, ac = (tid&3)*4;
    const float* Qb = g_qt + (size_t)b*LL*DD + h*EE;
    const float* Kb = g_kt + (size_t)b*LL*DD + h*EE;
    float acc[4][4] = {};
    for (int e0=0;e0<EE;e0+=16){
        float4 qv = *(const float4*)&Qb[(size_t)(t0+ar)*DD + e0 + ac];
        Qs[ac+0][ar]=qv.x; Qs[ac+1][ar]=qv.y; Qs[ac+2][ar]=qv.z; Qs[ac+3][ar]=qv.w;
        float4 kv = *(const float4*)&Kb[(size_t)(s0+ar)*DD + e0 + ac];
        Ks[ac+0][ar]=kv.x; Ks[ac+1][ar]=kv.y; Ks[ac+2][ar]=kv.z; Ks[ac+3][ar]=kv.w;
        __syncthreads();
        #pragma unroll
        for (int k=0;k<16;k++){
            float a[4], bv[4];
            *(float4*)a  = *(float4*)&Qs[k][ty*4];
            *(float4*)bv = *(float4*)&Ks[k][tx*4];
            #pragma unroll
            for (int i=0;i<4;i++)
                #pragma unroll
                for (int j=0;j<4;j++)
                    acc[i][j] += a[i]*bv[j];
        }
        __syncthreads();
    }
    float* Sb = g_S + (size_t)bh*LL*LL;
    #pragma unroll
    for (int i=0;i<4;i++)
        #pragma unroll
        for (int j=0;j<4;j++)
            Sb[(size_t)(t0+ty*4+i)*LL + s0 + tx*4 + j] = acc[i][j];
}

// ---------------- mean_value[b,tau] = (1/D) sum_h sum_t S[b,h,t,(t-tau)%L] ----------------
__global__ void meanval_k(){
    int b = blockIdx.x; int tau = threadIdx.x;
    float acc = 0.f;
    for (int h=0;h<HH;h++){
        const float* Sb = g_S + (size_t)(b*HH + h)*LL*LL;
        for (int t=0;t<LL;t++) acc += Sb[(size_t)t*LL + ((t - tau) & (LL-1))];
    }
    g_mv[b*LL + tau] = acc * (1.0f/DD);
}

// ---------------- top-5 delays of batch-mean ----------------
__global__ void topk_k(){
    __shared__ float sc[LL];
    int tau = threadIdx.x;
    float a = 0.f;
    for (int b=0;b<BB;b++) a += g_mv[b*LL + tau];
    sc[tau] = a * (1.0f/BB);
    __syncthreads();
    if (tau == 0){
        for (int j=0;j<KTOP;j++){
            float best = -1e30f; int bi = 0;
            for (int i=0;i<LL;i++) if (sc[i] > best){ best = sc[i]; bi = i; }
            g_delays[j] = bi;
            sc[bi] = -1e30f;
        }
    }
}

// ---------------- per-batch softmax over the 5 selected delays ----------------
__global__ void weights_k(){
    int b = threadIdx.x;
    float v[KTOP]; float mx = -1e30f;
    #pragma unroll
    for (int j=0;j<KTOP;j++){ v[j] = g_mv[b*LL + g_delays[j]]; mx = fmaxf(mx, v[j]); }
    float s = 0.f;
    #pragma unroll
    for (int j=0;j<KTOP;j++){ v[j] = expf(v[j]-mx); s += v[j]; }
    #pragma unroll
    for (int j=0;j<KTOP;j++) g_w[b*KTOP + j] = v[j]/s;
}

// ---------------- row softmax of S/sqrt(E)+mask, in place ----------------
__global__ void softmax_k(const int* __restrict__ paths){
    int row = blockIdx.x;          // (b*H+h)*L + t
    int b = row >> 9;
    int s = threadIdx.x;
    size_t off = (size_t)row*LL + s;
    float m = (paths[b*LL + s] < NTOT) ? 0.f : -10000.f;
    float v = g_S[off]*0.125f + m;
    __shared__ float red[8];
    float w = v;
    #pragma unroll
    for (int o=16;o;o>>=1) w = fmaxf(w, __shfl_xor_sync(0xffffffffu, w, o));
    if ((s&31)==0) red[s>>5] = w;
    __syncthreads();
    float mx = red[0];
    #pragma unroll
    for (int i=1;i<8;i++) mx = fmaxf(mx, red[i]);
    float e = expf(v - mx);
    float ws = e;
    #pragma unroll
    for (int o=16;o;o>>=1) ws += __shfl_xor_sync(0xffffffffu, ws, o);
    __syncthreads();
    if ((s&31)==0) red[s>>5] = ws;
    __syncthreads();
    float sum = 0.f;
    #pragma unroll
    for (int i=0;i<8;i++) sum += red[i];
    g_S[off] = e / sum;
}

// ---------------- spatial = att @ Vt_h  -> g_sp (B,H,L,E) ----------------
__global__ void __launch_bounds__(256) spatial_k(){
    __shared__ float As[16][64];
    __shared__ float Bs[16][64];
    int bh = blockIdx.y; int b = bh>>1, h = bh&1;
    int t0 = blockIdx.x*64;
    int tid = threadIdx.x;
    int ty = tid>>4, tx = tid&15;
    int ar = tid>>2, ac = (tid&3)*4;
    int br = tid>>4, bc = (tid&15)*4;
    const float* Sb = g_S  + (size_t)bh*LL*LL;
    const float* Vb = g_vt + (size_t)b*LL*DD + h*EE;
    float acc[4][4] = {};
    for (int s0=0;s0<LL;s0+=16){
        float4 av = *(const float4*)&Sb[(size_t)(t0+ar)*LL + s0 + ac];
        As[ac+0][ar]=av.x; As[ac+1][ar]=av.y; As[ac+2][ar]=av.z; As[ac+3][ar]=av.w;
        *(float4*)&Bs[br][bc] = *(const float4*)&Vb[(size_t)(s0+br)*DD + bc];
        __syncthreads();
        #pragma unroll
        for (int k=0;k<16;k++){
            float a[4], bv[4];
            *(float4*)a  = *(float4*)&As[k][ty*4];
            *(float4*)bv = *(float4*)&Bs[k][tx*4];
            #pragma unroll
            for (int i=0;i<4;i++)
                #pragma unroll
                for (int j=0;j<4;j++)
                    acc[i][j] += a[i]*bv[j];
        }
        __syncthreads();
    }
    #pragma unroll
    for (int i=0;i<4;i++)
        #pragma unroll
        for (int j=0;j<4;j++)
            g_sp[((size_t)bh*LL + t0+ty*4+i)*EE + tx*4 + j] = acc[i][j];
}

// ---------------- out = 0.9*freq(delay-gather of V) + 0.1*spatial ----------------
__global__ void combine_k(){
    int bt = blockIdx.x; int b = bt >> 8; int t = bt & (LL-1);
    int d = threadIdx.x; int h = d >> 6, e = d & 63;
    float sp = g_sp[((size_t)(b*HH+h)*LL + t)*EE + e];
    float fr = 0.f;
    #pragma unroll
    for (int j=0;j<KTOP;j++){
        int tt = (t + g_delays[j]) & (LL-1);
        fr += g_w[b*KTOP + j] * g_v[((size_t)b*LL + tt)*DD + d];
    }
    g_ao[(size_t)bt*DD + d] = 0.9f*fr + 0.1f*sp;
}

// ---------------- final gather: out[b] = x[b, lengths[b]-1] ----------------
__global__ void gather_k(const int* __restrict__ lengths, float* __restrict__ out){
    int b = blockIdx.x, d = threadIdx.x;
    int t = lengths[b] - 1;
    out[b*DD + d] = g_x[((size_t)b*LL + t)*DD + d];
}

// =====================================================================
extern "C" void kernel_launch(void* const* d_in, const int* in_sizes, int n_in,
                              void* d_out, int out_size){
    (void)in_sizes; (void)n_in; (void)out_size;
    const int*   paths   = (const int*)  d_in[0];
    const int*   lengths = (const int*)  d_in[1];
    const float* ego     = (const float*)d_in[4];
    const float* pos     = (const float*)d_in[5];
    const float* Wq      = (const float*)d_in[6];
    const float* Wk      = (const float*)d_in[7];
    const float* Wv      = (const float*)d_in[8];
    const float* Wp      = (const float*)d_in[9];
    const float* F1      = (const float*)d_in[10];
    const float* F2      = (const float*)d_in[11];
    float* outp = (float*)d_out;

    embed_k<<<MROWS, DD>>>(paths, ego, pos);

    const int lefts[2]  = {51, 0};
    const int rights[2] = {129, 78};
    dim3 g2(MROWS/64, 2), g4(MROWS/64, 4);

    for (int k = 0; k < 2; k++){
        filt_k<<<1, LL>>>(lefts[k], rights[k]);
        circ_k<<<dim3(4,2,BB), 256>>>();                                      // xf = C x
        gemm_k<<<g2,256>>>(Wq + (size_t)k*DD*DD, 1, 2, -1, DD, DD, 0);        // qt = xf@Wq
        gemm_k<<<g2,256>>>(Wk + (size_t)k*DD*DD, 1, 3, -1, DD, DD, 0);        // kt = xf@Wk
        gemm_k<<<g2,256>>>(Wv + (size_t)k*DD*DD, 1, 4, -1, DD, DD, 0);        // vt = xf@Wv
        gemm_k<<<g2,256>>>(Wv + (size_t)k*DD*DD, 0, 5, -1, DD, DD, 0);        // v  = x @Wv
        score_k<<<dim3(4,4,BB*HH), 256>>>();                                  // S = qt kt^T
        meanval_k<<<BB, LL>>>();
        topk_k<<<1, LL>>>();
        weights_k<<<1, BB>>>();
        softmax_k<<<BB*HH*LL, LL>>>(paths);                                   // S -> att
        spatial_k<<<dim3(4, BB*HH), 256>>>();                                 // sp = att@vt
        combine_k<<<MROWS, DD>>>();                                           // ao = 0.9 freq + 0.1 sp
        gemm_k<<<g2,256>>>(Wp + (size_t)k*DD*DD,     6, 7,  0, DD,   DD,   1);// a = ao@Wp + x
        gemm_k<<<g4,256>>>(F1 + (size_t)k*DD*2*DD,   7, 8, -1, DD,   2*DD, 2);// h = gelu(a@F1)
        gemm_k<<<g2,256>>>(F2 + (size_t)k*2*DD*DD,   8, 0, -1, 2*DD, DD,   0);// x = h@F2
    }
    gather_k<<<BB, DD>>>(lengths, outp);
}

// round 2
// speedup vs baseline: 1.1329x; 1.1329x over previous
#include <cuda_runtime.h>
#include <math.h>

#define BB 256
#define LL 256
#define DD 128
#define HH 2
#define EE 64
#define MROWS (BB*LL)     // 65536
#define KTOP 5
#define NTOT 100000

// ---------------- scratch (static device globals; no allocation) ----------------
static __device__ float g_x   [MROWS*DD];
static __device__ float g_xf  [MROWS*DD];
static __device__ float g_qkvt[MROWS*384];      // packed qt|kt|vt
static __device__ float g_v   [MROWS*DD];
static __device__ float g_ao  [MROWS*DD];
static __device__ float g_a   [MROWS*DD];
static __device__ float g_h   [MROWS*2*DD];
static __device__ float g_S   [BB*HH*LL*LL];    // 128MB
static __device__ float g_mv  [BB*LL];
static __device__ int   g_delays[KTOP];
static __device__ float g_w   [BB*KTOP];
static __device__ float g_hf  [LL];
static __device__ float g_C   [LL*LL];          // circulant matrix
static __device__ float g_wqkv[DD*384];         // packed weights

__device__ __forceinline__ float* bufsel(int s){
    switch(s){
        case 0: return g_x;   case 1: return g_xf; case 2: return g_qkvt;
        case 5: return g_v;   case 6: return g_ao; case 7: return g_a;
        default: return g_h;
    }
}

// ---------------- embedding ----------------
__global__ void embed_k(const int* __restrict__ paths,
                        const float* __restrict__ ego,
                        const float* __restrict__ pos){
    int bt = blockIdx.x; int t = bt & (LL-1); int d = threadIdx.x;
    int p = paths[bt];
    g_x[(size_t)bt*DD + d] = ego[(size_t)p*DD + d] + pos[t*DD + d];
}

// ---------------- band-pass impulse response ----------------
__global__ void filt_k(int l, int r){
    int n = threadIdx.x;
    double s = 0.0;
    for (int f = l; f < r; f++){
        double w = (f == 0 || f == LL/2) ? 1.0 : 2.0;
        s += w * cos(6.283185307179586477 * (double)(f*n) / (double)LL);
    }
    g_hf[n] = (float)(s / (double)LL);
}
__global__ void buildC_k(){
    int t = blockIdx.x, s = threadIdx.x;
    g_C[t*LL + s] = g_hf[(t - s) & (LL-1)];
}
__global__ void zero_mv_k(){
    g_mv[blockIdx.x*1024 + threadIdx.x] = 0.f;
}

// ---------------- circulant filter: Xf[b] = C @ X[b]  (128x64 tile, 8x4 micro) ----------------
__global__ void __launch_bounds__(256) circ_k(){
    __shared__ float As[16][128];
    __shared__ float Bs[16][64];
    int b = blockIdx.z;
    int t0 = blockIdx.x*128, d0 = blockIdx.y*64;
    int tid = threadIdx.x;
    int ty = tid>>4, tx = tid&15;
    int ar = tid>>1, ac = (tid&1)*8;
    int br = tid>>4, bc = (tid&15)*4;
    const float* Xb = g_x + (size_t)b*LL*DD;
    float acc[8][4] = {};
    for (int k0=0;k0<LL;k0+=16){
        float4 a0 = *(const float4*)&g_C[(size_t)(t0+ar)*LL + k0+ac];
        float4 a1 = *(const float4*)&g_C[(size_t)(t0+ar)*LL + k0+ac+4];
        As[ac+0][ar]=a0.x; As[ac+1][ar]=a0.y; As[ac+2][ar]=a0.z; As[ac+3][ar]=a0.w;
        As[ac+4][ar]=a1.x; As[ac+5][ar]=a1.y; As[ac+6][ar]=a1.z; As[ac+7][ar]=a1.w;
        *(float4*)&Bs[br][bc] = *(const float4*)&Xb[(size_t)(k0+br)*DD + d0 + bc];
        __syncthreads();
        #pragma unroll
        for (int k=0;k<16;k++){
            float a[8], bv[4];
            *(float4*)&a[0] = *(float4*)&As[k][ty*8];
            *(float4*)&a[4] = *(float4*)&As[k][ty*8+4];
            *(float4*)bv = *(float4*)&Bs[k][tx*4];
            #pragma unroll
            for (int i=0;i<8;i++)
                #pragma unroll
                for (int j=0;j<4;j++)
                    acc[i][j] += a[i]*bv[j];
        }
        __syncthreads();
    }
    float* Yb = g_xf + (size_t)b*LL*DD;
    #pragma unroll
    for (int i=0;i<8;i++){
        float4 o = {acc[i][0],acc[i][1],acc[i][2],acc[i][3]};
        *(float4*)&Yb[(size_t)(t0+ty*8+i)*DD + d0 + tx*4] = o;
    }
}

// ---------------- generic GEMM: C(M,N) = act(A(M,K) @ W(K,N) [+R]), 128x64 tile, 8x4 micro ----------------
// act: 0 none, 1 residual add (R stride N), 2 gelu
__global__ void __launch_bounds__(256) gemm_k(const float* __restrict__ Wp,
        int asel, int csel, int rsel, int wsel, int K, int N, int act){
    __shared__ float As[16][128];
    __shared__ float Bs[16][64];
    const float* A = bufsel(asel);
    float* C = bufsel(csel);
    const float* R = (rsel >= 0) ? bufsel(rsel) : (const float*)0;
    const float* W = (wsel >= 0) ? g_wqkv : Wp;
    int bm = blockIdx.x*128, bn = blockIdx.y*64;
    int tid = threadIdx.x;
    int ty = tid>>4, tx = tid&15;
    int ar = tid>>1, ac = (tid&1)*8;
    int br = tid>>4, bc = (tid&15)*4;
    float acc[8][4] = {};
    for (int k0=0;k0<K;k0+=16){
        float4 a0 = *(const float4*)&A[(size_t)(bm+ar)*K + k0+ac];
        float4 a1 = *(const float4*)&A[(size_t)(bm+ar)*K + k0+ac+4];
        As[ac+0][ar]=a0.x; As[ac+1][ar]=a0.y; As[ac+2][ar]=a0.z; As[ac+3][ar]=a0.w;
        As[ac+4][ar]=a1.x; As[ac+5][ar]=a1.y; As[ac+6][ar]=a1.z; As[ac+7][ar]=a1.w;
        *(float4*)&Bs[br][bc] = *(const float4*)&W[(size_t)(k0+br)*N + bn + bc];
        __syncthreads();
        #pragma unroll
        for (int k=0;k<16;k++){
            float a[8], bv[4];
            *(float4*)&a[0] = *(float4*)&As[k][ty*8];
            *(float4*)&a[4] = *(float4*)&As[k][ty*8+4];
            *(float4*)bv = *(float4*)&Bs[k][tx*4];
            #pragma unroll
            for (int i=0;i<8;i++)
                #pragma unroll
                for (int j=0;j<4;j++)
                    acc[i][j] += a[i]*bv[j];
        }
        __syncthreads();
    }
    #pragma unroll
    for (int i=0;i<8;i++){
        size_t r = (size_t)(bm + ty*8 + i);
        #pragma unroll
        for (int j=0;j<4;j++){
            int c = bn + tx*4 + j;
            float v = acc[i][j];
            if (act == 1) v += R[r*N + c];
            else if (act == 2) v = 0.5f*v*(1.0f + erff(v*0.70710678118654752f));
            C[r*N + c] = v;
        }
    }
}

// ---------------- pack Wq|Wk|Wv for layer k ----------------
__global__ void packw_k(const float* __restrict__ Wq, const float* __restrict__ Wk,
                        const float* __restrict__ Wv){
    int row = blockIdx.x, c = threadIdx.x;
    const float* src = (c < 128) ? Wq : (c < 256) ? Wk : Wv;
    g_wqkv[row*384 + c] = src[row*DD + (c & 127)];
}

// ---------------- score + mean_value: S = Qt Kt^T, mv += diag-sums ----------------
__global__ void __launch_bounds__(256) score_mv_k(){
    __shared__ float Qs[16][64];
    __shared__ float Ks[16][64];
    __shared__ float Ssm[64][65];
    int bh = blockIdx.z; int b = bh>>1, h = bh&1;
    int t0 = blockIdx.x*64, s0 = blockIdx.y*64;
    int tid = threadIdx.x;
    int ty = tid>>4, tx = tid&15;
    int ar = tid>>2, ac = (tid&3)*4;
    const float* Qb = g_qkvt + (size_t)b*LL*384 + h*EE;
    const float* Kb = g_qkvt + (size_t)b*LL*384 + 128 + h*EE;
    float acc[4][4] = {};
    for (int e0=0;e0<EE;e0+=16){
        float4 qv = *(const float4*)&Qb[(size_t)(t0+ar)*384 + e0 + ac];
        Qs[ac+0][ar]=qv.x; Qs[ac+1][ar]=qv.y; Qs[ac+2][ar]=qv.z; Qs[ac+3][ar]=qv.w;
        float4 kv = *(const float4*)&Kb[(size_t)(s0+ar)*384 + e0 + ac];
        Ks[ac+0][ar]=kv.x; Ks[ac+1][ar]=kv.y; Ks[ac+2][ar]=kv.z; Ks[ac+3][ar]=kv.w;
        __syncthreads();
        #pragma unroll
        for (int k=0;k<16;k++){
            float a[4], bv[4];
            *(float4*)a  = *(float4*)&Qs[k][ty*4];
            *(float4*)bv = *(float4*)&Ks[k][tx*4];
            #pragma unroll
            for (int i=0;i<4;i++)
                #pragma unroll
                for (int j=0;j<4;j++)
                    acc[i][j] += a[i]*bv[j];
        }
        __syncthreads();
    }
    #pragma unroll
    for (int i=0;i<4;i++)
        #pragma unroll
        for (int j=0;j<4;j++)
            Ssm[ty*4+i][tx*4+j] = acc[i][j];
    __syncthreads();
    // coalesced store of S
    {
        int r = tid>>2, c = (tid&3)*16;
        float* So = g_S + ((size_t)bh*LL + t0 + r)*LL + s0 + c;
        #pragma unroll
        for (int j=0;j<16;j+=4){
            float4 o = {Ssm[r][c+j],Ssm[r][c+j+1],Ssm[r][c+j+2],Ssm[r][c+j+3]};
            *(float4*)&So[j] = o;
        }
    }
    // diagonal sums -> mean_value
    if (tid < 127){
        int d = tid - 63;               // d = i - j
        int ilo = d > 0 ? d : 0;
        int ihi = d < 0 ? 63 + d : 63;
        float s = 0.f;
        for (int i = ilo; i <= ihi; i++) s += Ssm[i][i - d];
        int tau = (t0 - s0 + d) & (LL-1);
        atomicAdd(&g_mv[b*LL + tau], s * (1.0f/DD));
    }
}

// ---------------- top-5 delays ----------------
__global__ void topk_k(){
    __shared__ float sc[LL];
    int tau = threadIdx.x;
    float a = 0.f;
    for (int b=0;b<BB;b++) a += g_mv[b*LL + tau];
    sc[tau] = a * (1.0f/BB);
    __syncthreads();
    if (tau == 0){
        for (int j=0;j<KTOP;j++){
            float best = -1e30f; int bi = 0;
            for (int i=0;i<LL;i++) if (sc[i] > best){ best = sc[i]; bi = i; }
            g_delays[j] = bi;
            sc[bi] = -1e30f;
        }
    }
}
__global__ void weights_k(){
    int b = threadIdx.x;
    float v[KTOP]; float mx = -1e30f;
    #pragma unroll
    for (int j=0;j<KTOP;j++){ v[j] = g_mv[b*LL + g_delays[j]]; mx = fmaxf(mx, v[j]); }
    float s = 0.f;
    #pragma unroll
    for (int j=0;j<KTOP;j++){ v[j] = expf(v[j]-mx); s += v[j]; }
    #pragma unroll
    for (int j=0;j<KTOP;j++) g_w[b*KTOP + j] = v[j]/s;
}

// ---------------- fused: softmax(S) @ Vt, + freq combine -> g_ao ----------------
#define SP 257
__global__ void __launch_bounds__(256) attn_k(const int* __restrict__ paths){
    extern __shared__ float sm[];
    float* Ssm = sm;                    // 64 x 257
    float* Vs  = sm + 64*SP;            // 16 x 64
    float* msk = Vs + 16*64;            // 256
    int bh = blockIdx.y; int b = bh>>1, h = bh&1;
    int t0 = blockIdx.x*64;
    int tid = threadIdx.x;
    msk[tid] = (paths[b*LL + tid] < NTOT) ? 0.f : -10000.f;
    __syncthreads();
    // phase 1: load S rows, scale+mask, softmax in smem (4 threads per row)
    {
        int r = tid>>2, q = tid&3;
        const float* Srow = g_S + ((size_t)bh*LL + t0 + r)*LL + q*64;
        float mx = -1e30f;
        #pragma unroll
        for (int c=0;c<64;c+=4){
            float4 sv = *(const float4*)&Srow[c];
            float v0 = sv.x*0.125f + msk[q*64+c+0];
            float v1 = sv.y*0.125f + msk[q*64+c+1];
            float v2 = sv.z*0.125f + msk[q*64+c+2];
            float v3 = sv.w*0.125f + msk[q*64+c+3];
            Ssm[r*SP + q*64+c+0] = v0; Ssm[r*SP + q*64+c+1] = v1;
            Ssm[r*SP + q*64+c+2] = v2; Ssm[r*SP + q*64+c+3] = v3;
            mx = fmaxf(mx, fmaxf(fmaxf(v0,v1), fmaxf(v2,v3)));
        }
        mx = fmaxf(mx, __shfl_xor_sync(0xffffffffu, mx, 1));
        mx = fmaxf(mx, __shfl_xor_sync(0xffffffffu, mx, 2));
        float sum = 0.f;
        #pragma unroll
        for (int c=0;c<64;c++){
            float e = expf(Ssm[r*SP + q*64+c] - mx);
            Ssm[r*SP + q*64+c] = e;
            sum += e;
        }
        sum += __shfl_xor_sync(0xffffffffu, sum, 1);
        sum += __shfl_xor_sync(0xffffffffu, sum, 2);
        float inv = 1.0f/sum;
        #pragma unroll
        for (int c=0;c<64;c++) Ssm[r*SP + q*64+c] *= inv;
    }
    // phase 2: P @ Vt
    int ty = tid>>4, tx = tid&15;
    float acc[4][4] = {};
    for (int s0=0;s0<LL;s0+=16){
        __syncthreads();
        int br = tid>>4, bc = (tid&15)*4;
        *(float4*)&Vs[br*64+bc] =
            *(const float4*)&g_qkvt[((size_t)b*LL + s0 + br)*384 + 256 + h*EE + bc];
        __syncthreads();
        #pragma unroll
        for (int k=0;k<16;k++){
            float a[4], bv[4];
            #pragma unroll
            for (int i=0;i<4;i++) a[i] = Ssm[(ty*4+i)*SP + s0 + k];
            *(float4*)bv = *(float4*)&Vs[k*64 + tx*4];
            #pragma unroll
            for (int i=0;i<4;i++)
                #pragma unroll
                for (int j=0;j<4;j++)
                    acc[i][j] += a[i]*bv[j];
        }
    }
    // phase 3: epilogue with 0.9*freq + 0.1*spatial
    int d5[KTOP]; float w5[KTOP];
    #pragma unroll
    for (int j=0;j<KTOP;j++){ d5[j] = g_delays[j]; w5[j] = g_w[b*KTOP + j]; }
    #pragma unroll
    for (int i=0;i<4;i++){
        int t = t0 + ty*4 + i;
        float4 fr = {0,0,0,0};
        #pragma unroll
        for (int j=0;j<KTOP;j++){
            int tt = (t + d5[j]) & (LL-1);
            float4 vv = *(const float4*)&g_v[((size_t)b*LL + tt)*DD + h*EE + tx*4];
            fr.x += w5[j]*vv.x; fr.y += w5[j]*vv.y;
            fr.z += w5[j]*vv.z; fr.w += w5[j]*vv.w;
        }
        float4 o = {0.9f*fr.x + 0.1f*acc[i][0], 0.9f*fr.y + 0.1f*acc[i][1],
                    0.9f*fr.z + 0.1f*acc[i][2], 0.9f*fr.w + 0.1f*acc[i][3]};
        *(float4*)&g_ao[((size_t)b*LL + t)*DD + h*EE + tx*4] = o;
    }
}

// ---------------- final gather ----------------
__global__ void gather_k(const int* __restrict__ lengths, float* __restrict__ out){
    int b = blockIdx.x, d = threadIdx.x;
    int t = lengths[b] - 1;
    out[b*DD + d] = g_x[((size_t)b*LL + t)*DD + d];
}

// =====================================================================
extern "C" void kernel_launch(void* const* d_in, const int* in_sizes, int n_in,
                              void* d_out, int out_size){
    (void)in_sizes; (void)n_in; (void)out_size;
    const int*   paths   = (const int*)  d_in[0];
    const int*   lengths = (const int*)  d_in[1];
    const float* ego     = (const float*)d_in[4];
    const float* pos     = (const float*)d_in[5];
    const float* Wq      = (const float*)d_in[6];
    const float* Wk      = (const float*)d_in[7];
    const float* Wv      = (const float*)d_in[8];
    const float* Wp      = (const float*)d_in[9];
    const float* F1      = (const float*)d_in[10];
    const float* F2      = (const float*)d_in[11];
    float* outp = (float*)d_out;

    static bool attr_set = false;
    const int ATTN_SMEM = (64*SP + 16*64 + 256) * 4;
    if (!attr_set){
        cudaFuncSetAttribute(attn_k, cudaFuncAttributeMaxDynamicSharedMemorySize, ATTN_SMEM);
        attr_set = true;
    }

    embed_k<<<MROWS, DD>>>(paths, ego, pos);

    const int lefts[2]  = {51, 0};
    const int rights[2] = {129, 78};

    for (int k = 0; k < 2; k++){
        size_t wo = (size_t)k*DD*DD;
        filt_k<<<1, LL>>>(lefts[k], rights[k]);
        buildC_k<<<LL, LL>>>();
        circ_k<<<dim3(2,2,BB), 256>>>();                                       // xf = C x
        packw_k<<<DD, 384>>>(Wq + wo, Wk + wo, Wv + wo);
        gemm_k<<<dim3(512,6),256>>>(nullptr, 1, 2, -1, 0, DD, 384, 0);         // qkvt = xf@[Wq|Wk|Wv]
        gemm_k<<<dim3(512,2),256>>>(Wv + wo, 0, 5, -1, -1, DD, DD, 0);         // v = x@Wv
        zero_mv_k<<<64, 1024>>>();
        score_mv_k<<<dim3(4,4,BB*HH), 256>>>();                                // S + mean_value
        topk_k<<<1, LL>>>();
        weights_k<<<1, BB>>>();
        attn_k<<<dim3(4, BB*HH), 256, ATTN_SMEM>>>(paths);                     // softmax@Vt + combine
        gemm_k<<<dim3(512,2),256>>>(Wp + wo, 6, 7, 0, -1, DD, DD, 1);          // a = ao@Wp + x
        gemm_k<<<dim3(512,4),256>>>(F1 + (size_t)k*DD*2*DD, 7, 8, -1, -1, DD, 2*DD, 2); // h = gelu(a@F1)
        gemm_k<<<dim3(512,2),256>>>(F2 + (size_t)k*2*DD*DD, 8, 0, -1, -1, 2*DD, DD, 0); // x = h@F2
    }
    gather_k<<<BB, DD>>>(lengths, outp);
}

// round 5
// speedup vs baseline: 1.4499x; 1.2798x over previous
#include <cuda_runtime.h>
#include <cuda_bf16.h>
#include <math.h>
#include <stdint.h>

#define BB 256
#define LL 256
#define DD 128
#define HH 2
#define EE 64
#define MROWS (BB*LL)     // 65536
#define KTOP 5
#define NTOT 100000

// ---------------- scratch (static device globals; no allocation) ----------------
static __device__ float g_x   [MROWS*DD];
static __device__ float g_xf  [MROWS*DD];
static __device__ float g_qkvt[MROWS*384];      // packed qt|kt|vt
static __device__ float g_v   [MROWS*DD];
static __device__ float g_ao  [MROWS*DD];
static __device__ float g_a   [MROWS*DD];
static __device__ float g_h   [MROWS*2*DD];
static __device__ float g_S   [BB*HH*LL*LL];    // 128MB
static __device__ float g_mv  [BB*LL];
static __device__ int   g_delays[KTOP];
static __device__ float g_w   [BB*KTOP];
static __device__ float g_hf  [LL];
static __device__ float g_C   [LL*LL];          // circulant matrix
static __device__ float g_wT  [131072];         // transposed weights: qkvT|wpT|f1T|f2T

// ============================ mma helpers ============================
__device__ __forceinline__ uint32_t s2u(const void* p){
    uint32_t a;
    asm("{ .reg .u64 t; cvta.to.shared.u64 t, %1; cvt.u32.u64 %0, t; }" : "=r"(a) : "l"(p));
    return a;
}
__device__ __forceinline__ void ldm_x4(uint32_t& r0,uint32_t& r1,uint32_t& r2,uint32_t& r3,uint32_t addr){
    asm volatile("ldmatrix.sync.aligned.m8n8.x4.shared.b16 {%0,%1,%2,%3}, [%4];"
        : "=r"(r0),"=r"(r1),"=r"(r2),"=r"(r3) : "r"(addr));
}
__device__ __forceinline__ void mma16816(float* c, const uint32_t* a, const uint32_t* b){
    asm volatile("mma.sync.aligned.m16n8k16.row.col.f32.bf16.bf16.f32 "
        "{%0,%1,%2,%3}, {%4,%5,%6,%7}, {%8,%9}, {%0,%1,%2,%3};"
        : "+f"(c[0]),"+f"(c[1]),"+f"(c[2]),"+f"(c[3])
        : "r"(a[0]),"r"(a[1]),"r"(a[2]),"r"(a[3]), "r"(b[0]),"r"(b[1]));
}

// ======= tensor-core GEMM: C(Mtile=128, Ntile=64) = act(A@B^T [+R]) =======
// A: (M,K) row-major. B: (N,K) row-major if btrans=0; if btrans=1, B(n,k)=B[k*ldb+n].
// bf16 3-term split (hh+hl+lh) => ~fp32 accuracy. act: 0 none, 1 +R, 2 gelu.
#define PIT 40   // bf16 pitch (80 bytes): conflict-free ldmatrix
__global__ void __launch_bounds__(256) gemm_mma(
    const float* __restrict__ A, int lda, long sA,
    const float* __restrict__ B, int ldb, long sB, int btrans,
    float* __restrict__ C, int ldc, long sC,
    const float* __restrict__ R, int K, int act)
{
    __shared__ __nv_bfloat16 Ah[128*PIT], Al[128*PIT], Bh[64*PIT], Bl[64*PIT];
    int tid = threadIdx.x, lane = tid & 31, warp = tid >> 5;
    int wm = warp & 3, wn = warp >> 2;
    int bm = blockIdx.x*128, bn = blockIdx.y*64, z = blockIdx.z;
    A += (size_t)z * sA; B += (size_t)z * sB; C += (size_t)z * sC;

    float c[2][4][4] = {};
    uint32_t sAh = s2u(Ah), sAl = s2u(Al), sBh = s2u(Bh), sBl = s2u(Bl);

    // ldmatrix address components (per lane)
    int a_row = (lane & 7) + ((lane >> 3) & 1)*8;     // 0..15
    int a_koff = (lane >> 4)*8;                       // 0 or 8
    int b_nsel = lane >> 4;                           // ntile pair select
    int b_row  = lane & 7;
    int b_koff = ((lane >> 3) & 1)*8;

    for (int kc = 0; kc < K; kc += 32){
        // ---- A chunk: 128 rows x 32 k ----
        {
            int rr = tid >> 4, c2 = tid & 15;           // k = c2*2
            #pragma unroll
            for (int p = 0; p < 8; p++){
                int r = rr + p*16;
                float2 v = *(const float2*)&A[(size_t)(bm+r)*lda + kc + c2*2];
                __nv_bfloat16 h0 = __float2bfloat16_rn(v.x);
                __nv_bfloat16 h1 = __float2bfloat16_rn(v.y);
                __nv_bfloat16 l0 = __float2bfloat16_rn(v.x - __bfloat162float(h0));
                __nv_bfloat16 l1 = __float2bfloat16_rn(v.y - __bfloat162float(h1));
                *(__nv_bfloat162*)&Ah[r*PIT + c2*2] = __nv_bfloat162(h0, h1);
                *(__nv_bfloat162*)&Al[r*PIT + c2*2] = __nv_bfloat162(l0, l1);
            }
        }
        // ---- B chunk: 64 n-rows x 32 k ----
        if (!btrans){
            int rr = tid >> 4, c2 = tid & 15;
            #pragma unroll
            for (int p = 0; p < 4; p++){
                int r = rr + p*16;
                float2 v = *(const float2*)&B[(size_t)(bn+r)*ldb + kc + c2*2];
                __nv_bfloat16 h0 = __float2bfloat16_rn(v.x);
                __nv_bfloat16 h1 = __float2bfloat16_rn(v.y);
                __nv_bfloat16 l0 = __float2bfloat16_rn(v.x - __bfloat162float(h0));
                __nv_bfloat16 l1 = __float2bfloat16_rn(v.y - __bfloat162float(h1));
                *(__nv_bfloat162*)&Bh[r*PIT + c2*2] = __nv_bfloat162(h0, h1);
                *(__nv_bfloat162*)&Bl[r*PIT + c2*2] = __nv_bfloat162(l0, l1);
            }
        } else {
            int n = tid & 63, k0 = (tid >> 6)*8;
            #pragma unroll
            for (int j = 0; j < 8; j++){
                float v = B[(size_t)(kc + k0 + j)*ldb + bn + n];
                __nv_bfloat16 h = __float2bfloat16_rn(v);
                Bh[n*PIT + k0 + j] = h;
                Bl[n*PIT + k0 + j] = __float2bfloat16_rn(v - __bfloat162float(h));
            }
        }
        __syncthreads();

        #pragma unroll
        for (int ks = 0; ks < 2; ks++){
            int kb = ks*16;
            uint32_t ah[2][4], al[2][4], bh[4][2], bl[4][2];
            #pragma unroll
            for (int mt = 0; mt < 2; mt++){
                uint32_t off = (uint32_t)((wm*32 + mt*16 + a_row)*PIT + kb + a_koff)*2;
                ldm_x4(ah[mt][0], ah[mt][1], ah[mt][2], ah[mt][3], sAh + off);
                ldm_x4(al[mt][0], al[mt][1], al[mt][2], al[mt][3], sAl + off);
            }
            #pragma unroll
            for (int np = 0; np < 2; np++){   // ntile pair: covers nt=2*np, 2*np+1
                uint32_t off = (uint32_t)((wn*32 + np*16 + b_nsel*8 + b_row)*PIT + kb + b_koff)*2;
                ldm_x4(bh[2*np][0], bh[2*np][1], bh[2*np+1][0], bh[2*np+1][1], sBh + off);
                ldm_x4(bl[2*np][0], bl[2*np][1], bl[2*np+1][0], bl[2*np+1][1], sBl + off);
            }
            #pragma unroll
            for (int mt = 0; mt < 2; mt++)
                #pragma unroll
                for (int nt = 0; nt < 4; nt++){
                    mma16816(c[mt][nt], ah[mt], bh[nt]);
                    mma16816(c[mt][nt], ah[mt], bl[nt]);
                    mma16816(c[mt][nt], al[mt], bh[nt]);
                }
        }
        __syncthreads();
    }

    // ---- epilogue: fragment-direct float2 stores ----
    int r0 = lane >> 2, c0 = (lane & 3)*2;
    #pragma unroll
    for (int mt = 0; mt < 2; mt++)
        #pragma unroll
        for (int nt = 0; nt < 4; nt++)
            #pragma unroll
            for (int half = 0; half < 2; half++){
                size_t row = (size_t)(bm + wm*32 + mt*16 + r0 + half*8);
                int col = bn + wn*32 + nt*8 + c0;
                float v0 = c[mt][nt][half*2+0], v1 = c[mt][nt][half*2+1];
                if (act == 1){
                    v0 += R[row*ldc + col]; v1 += R[row*ldc + col + 1];
                } else if (act == 2){
                    v0 = 0.5f*v0*(1.0f + erff(v0*0.70710678118654752f));
                    v1 = 0.5f*v1*(1.0f + erff(v1*0.70710678118654752f));
                }
                *(float2*)&C[row*ldc + col] = make_float2(v0, v1);
            }
}

// ---------------- weight transpose: Wt[n][k] = W[k][n] ----------------
__global__ void transp_k(const float* __restrict__ W, int dstoff, int K, int N){
    int n = blockIdx.x;
    for (int k = threadIdx.x; k < K; k += blockDim.x)
        g_wT[dstoff + (size_t)n*K + k] = W[(size_t)k*N + n];
}

// ---------------- embedding ----------------
__global__ void embed_k(const int* __restrict__ paths,
                        const float* __restrict__ ego,
                        const float* __restrict__ pos){
    int bt = blockIdx.x; int t = bt & (LL-1); int d = threadIdx.x;
    int p = paths[bt];
    g_x[(size_t)bt*DD + d] = ego[(size_t)p*DD + d] + pos[t*DD + d];
}

// ---------------- band-pass impulse response + circulant matrix ----------------
__global__ void filt_k(int l, int r){
    int n = threadIdx.x;
    double s = 0.0;
    for (int f = l; f < r; f++){
        double w = (f == 0 || f == LL/2) ? 1.0 : 2.0;
        s += w * cos(6.283185307179586477 * (double)(f*n) / (double)LL);
    }
    g_hf[n] = (float)(s / (double)LL);
}
__global__ void buildC_k(){
    int t = blockIdx.x, s = threadIdx.x;
    g_C[t*LL + s] = g_hf[(t - s) & (LL-1)];
}
__global__ void zero_mv_k(){
    g_mv[blockIdx.x*1024 + threadIdx.x] = 0.f;
}

// ---------------- score + mean_value: S = Qt Kt^T, mv += diag-sums ----------------
__global__ void __launch_bounds__(256) score_mv_k(){
    __shared__ float Qs[16][64];
    __shared__ float Ks[16][64];
    __shared__ float Ssm[64][65];
    int bh = blockIdx.z; int b = bh>>1, h = bh&1;
    int t0 = blockIdx.x*64, s0 = blockIdx.y*64;
    int tid = threadIdx.x;
    int ty = tid>>4, tx = tid&15;
    int ar = tid>>2, ac = (tid&3)*4;
    const float* Qb = g_qkvt + (size_t)b*LL*384 + h*EE;
    const float* Kb = g_qkvt + (size_t)b*LL*384 + 128 + h*EE;
    float acc[4][4] = {};
    for (int e0=0;e0<EE;e0+=16){
        float4 qv = *(const float4*)&Qb[(size_t)(t0+ar)*384 + e0 + ac];
        Qs[ac+0][ar]=qv.x; Qs[ac+1][ar]=qv.y; Qs[ac+2][ar]=qv.z; Qs[ac+3][ar]=qv.w;
        float4 kv = *(const float4*)&Kb[(size_t)(s0+ar)*384 + e0 + ac];
        Ks[ac+0][ar]=kv.x; Ks[ac+1][ar]=kv.y; Ks[ac+2][ar]=kv.z; Ks[ac+3][ar]=kv.w;
        __syncthreads();
        #pragma unroll
        for (int k=0;k<16;k++){
            float a[4], bv[4];
            *(float4*)a  = *(float4*)&Qs[k][ty*4];
            *(float4*)bv = *(float4*)&Ks[k][tx*4];
            #pragma unroll
            for (int i=0;i<4;i++)
                #pragma unroll
                for (int j=0;j<4;j++)
                    acc[i][j] += a[i]*bv[j];
        }
        __syncthreads();
    }
    #pragma unroll
    for (int i=0;i<4;i++)
        #pragma unroll
        for (int j=0;j<4;j++)
            Ssm[ty*4+i][tx*4+j] = acc[i][j];
    __syncthreads();
    {
        int r = tid>>2, c = (tid&3)*16;
        float* So = g_S + ((size_t)bh*LL + t0 + r)*LL + s0 + c;
        #pragma unroll
        for (int j=0;j<16;j+=4){
            float4 o = {Ssm[r][c+j],Ssm[r][c+j+1],Ssm[r][c+j+2],Ssm[r][c+j+3]};
            *(float4*)&So[j] = o;
        }
    }
    if (tid < 127){
        int d = tid - 63;
        int ilo = d > 0 ? d : 0;
        int ihi = d < 0 ? 63 + d : 63;
        float s = 0.f;
        for (int i = ilo; i <= ihi; i++) s += Ssm[i][i - d];
        int tau = (t0 - s0 + d) & (LL-1);
        atomicAdd(&g_mv[b*LL + tau], s * (1.0f/DD));
    }
}

// ---------------- top-5 delays ----------------
__global__ void topk_k(){
    __shared__ float sc[LL];
    int tau = threadIdx.x;
    float a = 0.f;
    for (int b=0;b<BB;b++) a += g_mv[b*LL + tau];
    sc[tau] = a * (1.0f/BB);
    __syncthreads();
    if (tau == 0){
        for (int j=0;j<KTOP;j++){
            float best = -1e30f; int bi = 0;
            for (int i=0;i<LL;i++) if (sc[i] > best){ best = sc[i]; bi = i; }
            g_delays[j] = bi;
            sc[bi] = -1e30f;
        }
    }
}
__global__ void weights_k(){
    int b = threadIdx.x;
    float v[KTOP]; float mx = -1e30f;
    #pragma unroll
    for (int j=0;j<KTOP;j++){ v[j] = g_mv[b*LL + g_delays[j]]; mx = fmaxf(mx, v[j]); }
    float s = 0.f;
    #pragma unroll
    for (int j=0;j<KTOP;j++){ v[j] = expf(v[j]-mx); s += v[j]; }
    #pragma unroll
    for (int j=0;j<KTOP;j++) g_w[b*KTOP + j] = v[j]/s;
}

// ---------------- fused: softmax(S) @ Vt, + freq combine -> g_ao ----------------
#define SP 257
__global__ void __launch_bounds__(256) attn_k(const int* __restrict__ paths){
    extern __shared__ float sm[];
    float* Ssm = sm;                    // 64 x 257
    float* Vs  = sm + 64*SP;            // 16 x 64
    float* msk = Vs + 16*64;            // 256
    int bh = blockIdx.y; int b = bh>>1, h = bh&1;
    int t0 = blockIdx.x*64;
    int tid = threadIdx.x;
    msk[tid] = (paths[b*LL + tid] < NTOT) ? 0.f : -10000.f;
    __syncthreads();
    {
        int r = tid>>2, q = tid&3;
        const float* Srow = g_S + ((size_t)bh*LL + t0 + r)*LL + q*64;
        float mx = -1e30f;
        #pragma unroll
        for (int c=0;c<64;c+=4){
            float4 sv = *(const float4*)&Srow[c];
            float v0 = sv.x*0.125f + msk[q*64+c+0];
            float v1 = sv.y*0.125f + msk[q*64+c+1];
            float v2 = sv.z*0.125f + msk[q*64+c+2];
            float v3 = sv.w*0.125f + msk[q*64+c+3];
            Ssm[r*SP + q*64+c+0] = v0; Ssm[r*SP + q*64+c+1] = v1;
            Ssm[r*SP + q*64+c+2] = v2; Ssm[r*SP + q*64+c+3] = v3;
            mx = fmaxf(mx, fmaxf(fmaxf(v0,v1), fmaxf(v2,v3)));
        }
        mx = fmaxf(mx, __shfl_xor_sync(0xffffffffu, mx, 1));
        mx = fmaxf(mx, __shfl_xor_sync(0xffffffffu, mx, 2));
        float sum = 0.f;
        #pragma unroll
        for (int c=0;c<64;c++){
            float e = expf(Ssm[r*SP + q*64+c] - mx);
            Ssm[r*SP + q*64+c] = e;
            sum += e;
        }
        sum += __shfl_xor_sync(0xffffffffu, sum, 1);
        sum += __shfl_xor_sync(0xffffffffu, sum, 2);
        float inv = 1.0f/sum;
        #pragma unroll
        for (int c=0;c<64;c++) Ssm[r*SP + q*64+c] *= inv;
    }
    int ty = tid>>4, tx = tid&15;
    float acc[4][4] = {};
    for (int s0=0;s0<LL;s0+=16){
        __syncthreads();
        int br = tid>>4, bc = (tid&15)*4;
        *(float4*)&Vs[br*64+bc] =
            *(const float4*)&g_qkvt[((size_t)b*LL + s0 + br)*384 + 256 + h*EE + bc];
        __syncthreads();
        #pragma unroll
        for (int k=0;k<16;k++){
            float a[4], bv[4];
            #pragma unroll
            for (int i=0;i<4;i++) a[i] = Ssm[(ty*4+i)*SP + s0 + k];
            *(float4*)bv = *(float4*)&Vs[k*64 + tx*4];
            #pragma unroll
            for (int i=0;i<4;i++)
                #pragma unroll
                for (int j=0;j<4;j++)
                    acc[i][j] += a[i]*bv[j];
        }
    }
    int d5[KTOP]; float w5[KTOP];
    #pragma unroll
    for (int j=0;j<KTOP;j++){ d5[j] = g_delays[j]; w5[j] = g_w[b*KTOP + j]; }
    #pragma unroll
    for (int i=0;i<4;i++){
        int t = t0 + ty*4 + i;
        float4 fr = {0,0,0,0};
        #pragma unroll
        for (int j=0;j<KTOP;j++){
            int tt = (t + d5[j]) & (LL-1);
            float4 vv = *(const float4*)&g_v[((size_t)b*LL + tt)*DD + h*EE + tx*4];
            fr.x += w5[j]*vv.x; fr.y += w5[j]*vv.y;
            fr.z += w5[j]*vv.z; fr.w += w5[j]*vv.w;
        }
        float4 o = {0.9f*fr.x + 0.1f*acc[i][0], 0.9f*fr.y + 0.1f*acc[i][1],
                    0.9f*fr.z + 0.1f*acc[i][2], 0.9f*fr.w + 0.1f*acc[i][3]};
        *(float4*)&g_ao[((size_t)b*LL + t)*DD + h*EE + tx*4] = o;
    }
}

// ---------------- final gather ----------------
__global__ void gather_k(const int* __restrict__ lengths, float* __restrict__ out){
    int b = blockIdx.x, d = threadIdx.x;
    int t = lengths[b] - 1;
    out[b*DD + d] = g_x[((size_t)b*LL + t)*DD + d];
}

// =====================================================================
extern "C" void kernel_launch(void* const* d_in, const int* in_sizes, int n_in,
                              void* d_out, int out_size){
    (void)in_sizes; (void)n_in; (void)out_size;
    const int*   paths   = (const int*)  d_in[0];
    const int*   lengths = (const int*)  d_in[1];
    const float* ego     = (const float*)d_in[4];
    const float* pos     = (const float*)d_in[5];
    const float* Wq      = (const float*)d_in[6];
    const float* Wk      = (const float*)d_in[7];
    const float* Wv      = (const float*)d_in[8];
    const float* Wp      = (const float*)d_in[9];
    const float* F1      = (const float*)d_in[10];
    const float* F2      = (const float*)d_in[11];
    float* outp = (float*)d_out;

    const int ATTN_SMEM = (64*SP + 16*64 + 256) * 4;
    static bool init_done = false;
    static float *px, *pxf, *pqkvt, *pv, *pao, *pa, *ph, *pC, *pwT;
    if (!init_done){
        cudaFuncSetAttribute(attn_k, cudaFuncAttributeMaxDynamicSharedMemorySize, ATTN_SMEM);
        cudaGetSymbolAddress((void**)&px,   g_x);
        cudaGetSymbolAddress((void**)&pxf,  g_xf);
        cudaGetSymbolAddress((void**)&pqkvt,g_qkvt);
        cudaGetSymbolAddress((void**)&pv,   g_v);
        cudaGetSymbolAddress((void**)&pao,  g_ao);
        cudaGetSymbolAddress((void**)&pa,   g_a);
        cudaGetSymbolAddress((void**)&ph,   g_h);
        cudaGetSymbolAddress((void**)&pC,   g_C);
        cudaGetSymbolAddress((void**)&pwT,  g_wT);
        init_done = true;
    }

    embed_k<<<MROWS, DD>>>(paths, ego, pos);

    const int lefts[2]  = {51, 0};
    const int rights[2] = {129, 78};
    // g_wT offsets (floats): qkvT 0 (Wq^T|Wk^T|Wv^T, 384x128), wpT 49152, f1T 65536, f2T 98304
    for (int k = 0; k < 2; k++){
        size_t wo = (size_t)k*DD*DD;
        filt_k<<<1, LL>>>(lefts[k], rights[k]);
        buildC_k<<<LL, LL>>>();
        transp_k<<<128, 128>>>(Wq + wo,                 0,     128, 128);
        transp_k<<<128, 128>>>(Wk + wo,                 16384, 128, 128);
        transp_k<<<128, 128>>>(Wv + wo,                 32768, 128, 128);
        transp_k<<<128, 128>>>(Wp + wo,                 49152, 128, 128);
        transp_k<<<256, 128>>>(F1 + (size_t)k*DD*2*DD,  65536, 128, 256);
        transp_k<<<128, 256>>>(F2 + (size_t)k*2*DD*DD,  98304, 256, 128);

        // xf = C @ x   (per batch; B = x with transposed load)
        gemm_mma<<<dim3(2,2,BB), 256>>>(pC, LL, 0,  px, DD, (long)LL*DD, 1,
                                        pxf, DD, (long)LL*DD, nullptr, LL, 0);
        // qkvt = xf @ [Wq|Wk|Wv]
        gemm_mma<<<dim3(512,6,1), 256>>>(pxf, DD, 0,  pwT, DD, 0, 0,
                                         pqkvt, 384, 0, nullptr, DD, 0);
        // v = x @ Wv
        gemm_mma<<<dim3(512,2,1), 256>>>(px, DD, 0,  pwT + 32768, DD, 0, 0,
                                         pv, DD, 0, nullptr, DD, 0);
        zero_mv_k<<<64, 1024>>>();
        score_mv_k<<<dim3(4,4,BB*HH), 256>>>();
        topk_k<<<1, LL>>>();
        weights_k<<<1, BB>>>();
        attn_k<<<dim3(4, BB*HH), 256, ATTN_SMEM>>>(paths);
        // a = ao @ Wp + x
        gemm_mma<<<dim3(512,2,1), 256>>>(pao, DD, 0,  pwT + 49152, DD, 0, 0,
                                         pa, DD, 0, px, DD, 1);
        // h = gelu(a @ F1)
        gemm_mma<<<dim3(512,4,1), 256>>>(pa, DD, 0,  pwT + 65536, DD, 0, 0,
                                         ph, 2*DD, 0, nullptr, DD, 2);
        // x = h @ F2
        gemm_mma<<<dim3(512,2,1), 256>>>(ph, 2*DD, 0,  pwT + 98304, 2*DD, 0, 0,
                                         px, DD, 0, nullptr, 2*DD, 0);
    }
    gather_k<<<BB, DD>>>(lengths, outp);
}

// round 6
// speedup vs baseline: 1.5223x; 1.0499x over previous
#include <cuda_runtime.h>
#include <cuda_bf16.h>
#include <math.h>
#include <stdint.h>

#define BB 256
#define LL 256
#define DD 128
#define HH 2
#define EE 64
#define MROWS (BB*LL)     // 65536
#define KTOP 5
#define NTOT 100000

// ---------------- scratch (static device globals; no allocation) ----------------
static __device__ float g_x   [MROWS*DD];
static __device__ float g_xf  [MROWS*DD];
static __device__ float g_qkvt[MROWS*384];      // packed qt|kt|vt
static __device__ float g_v   [MROWS*DD];
static __device__ float g_ao  [MROWS*DD];
static __device__ float g_a   [MROWS*DD];
static __device__ float g_h   [MROWS*2*DD];
static __device__ float g_mv  [BB*LL];
static __device__ int   g_delays[KTOP];
static __device__ float g_w   [BB*KTOP];
static __device__ float g_hf  [2*LL];
static __device__ float g_C   [2*LL*LL];        // circulant matrices, both layers
static __device__ float g_wT  [262144];         // transposed weights, both layers

// ============================ mma helpers ============================
__device__ __forceinline__ uint32_t s2u(const void* p){
    uint32_t a;
    asm("{ .reg .u64 t; cvta.to.shared.u64 t, %1; cvt.u32.u64 %0, t; }" : "=r"(a) : "l"(p));
    return a;
}
__device__ __forceinline__ void ldm_x4(uint32_t& r0,uint32_t& r1,uint32_t& r2,uint32_t& r3,uint32_t addr){
    asm volatile("ldmatrix.sync.aligned.m8n8.x4.shared.b16 {%0,%1,%2,%3}, [%4];"
        : "=r"(r0),"=r"(r1),"=r"(r2),"=r"(r3) : "r"(addr));
}
__device__ __forceinline__ void mma16816(float* c, const uint32_t* a, const uint32_t* b){
    asm volatile("mma.sync.aligned.m16n8k16.row.col.f32.bf16.bf16.f32 "
        "{%0,%1,%2,%3}, {%4,%5,%6,%7}, {%8,%9}, {%0,%1,%2,%3};"
        : "+f"(c[0]),"+f"(c[1]),"+f"(c[2]),"+f"(c[3])
        : "r"(a[0]),"r"(a[1]),"r"(a[2]),"r"(a[3]), "r"(b[0]),"r"(b[1]));
}
__device__ __forceinline__ void bfsplit(float v, __nv_bfloat16& hi, __nv_bfloat16& lo){
    hi = __float2bfloat16_rn(v);
    lo = __float2bfloat16_rn(v - __bfloat162float(hi));
}

// ======= tensor-core GEMM: C(Mtile=128, Ntile=64) = act(A@B^T [+R]) =======
#define PIT 40   // bf16 pitch (80 bytes): conflict-free ldmatrix
__global__ void __launch_bounds__(256) gemm_mma(
    const float* __restrict__ A, int lda, long sA,
    const float* __restrict__ B, int ldb, long sB, int btrans,
    float* __restrict__ C, int ldc, long sC,
    const float* __restrict__ R, int K, int act)
{
    __shared__ __nv_bfloat16 Ah[128*PIT], Al[128*PIT], Bh[64*PIT], Bl[64*PIT];
    int tid = threadIdx.x, lane = tid & 31, warp = tid >> 5;
    int wm = warp & 3, wn = warp >> 2;
    int bm = blockIdx.x*128, bn = blockIdx.y*64, z = blockIdx.z;
    A += (size_t)z * sA; B += (size_t)z * sB; C += (size_t)z * sC;

    float c[2][4][4] = {};
    uint32_t sAh = s2u(Ah), sAl = s2u(Al), sBh = s2u(Bh), sBl = s2u(Bl);
    int a_row = (lane & 7) + ((lane >> 3) & 1)*8;
    int a_koff = (lane >> 4)*8;
    int b_nsel = lane >> 4;
    int b_row  = lane & 7;
    int b_koff = ((lane >> 3) & 1)*8;

    for (int kc = 0; kc < K; kc += 32){
        {
            int rr = tid >> 4, c2 = tid & 15;
            #pragma unroll
            for (int p = 0; p < 8; p++){
                int r = rr + p*16;
                float2 v = *(const float2*)&A[(size_t)(bm+r)*lda + kc + c2*2];
                __nv_bfloat16 h0,h1,l0,l1;
                bfsplit(v.x,h0,l0); bfsplit(v.y,h1,l1);
                *(__nv_bfloat162*)&Ah[r*PIT + c2*2] = __nv_bfloat162(h0, h1);
                *(__nv_bfloat162*)&Al[r*PIT + c2*2] = __nv_bfloat162(l0, l1);
            }
        }
        if (!btrans){
            int rr = tid >> 4, c2 = tid & 15;
            #pragma unroll
            for (int p = 0; p < 4; p++){
                int r = rr + p*16;
                float2 v = *(const float2*)&B[(size_t)(bn+r)*ldb + kc + c2*2];
                __nv_bfloat16 h0,h1,l0,l1;
                bfsplit(v.x,h0,l0); bfsplit(v.y,h1,l1);
                *(__nv_bfloat162*)&Bh[r*PIT + c2*2] = __nv_bfloat162(h0, h1);
                *(__nv_bfloat162*)&Bl[r*PIT + c2*2] = __nv_bfloat162(l0, l1);
            }
        } else {
            int n = tid & 63, k0 = (tid >> 6)*8;
            #pragma unroll
            for (int j = 0; j < 8; j++){
                float v = B[(size_t)(kc + k0 + j)*ldb + bn + n];
                __nv_bfloat16 h,l;
                bfsplit(v,h,l);
                Bh[n*PIT + k0 + j] = h;
                Bl[n*PIT + k0 + j] = l;
            }
        }
        __syncthreads();

        #pragma unroll
        for (int ks = 0; ks < 2; ks++){
            int kb = ks*16;
            uint32_t ah[2][4], al[2][4], bh[4][2], bl[4][2];
            #pragma unroll
            for (int mt = 0; mt < 2; mt++){
                uint32_t off = (uint32_t)((wm*32 + mt*16 + a_row)*PIT + kb + a_koff)*2;
                ldm_x4(ah[mt][0], ah[mt][1], ah[mt][2], ah[mt][3], sAh + off);
                ldm_x4(al[mt][0], al[mt][1], al[mt][2], al[mt][3], sAl + off);
            }
            #pragma unroll
            for (int np = 0; np < 2; np++){
                uint32_t off = (uint32_t)((wn*32 + np*16 + b_nsel*8 + b_row)*PIT + kb + b_koff)*2;
                ldm_x4(bh[2*np][0], bh[2*np][1], bh[2*np+1][0], bh[2*np+1][1], sBh + off);
                ldm_x4(bl[2*np][0], bl[2*np][1], bl[2*np+1][0], bl[2*np+1][1], sBl + off);
            }
            #pragma unroll
            for (int mt = 0; mt < 2; mt++)
                #pragma unroll
                for (int nt = 0; nt < 4; nt++){
                    mma16816(c[mt][nt], ah[mt], bh[nt]);
                    mma16816(c[mt][nt], ah[mt], bl[nt]);
                    mma16816(c[mt][nt], al[mt], bh[nt]);
                }
        }
        __syncthreads();
    }

    int r0 = lane >> 2, c0 = (lane & 3)*2;
    #pragma unroll
    for (int mt = 0; mt < 2; mt++)
        #pragma unroll
        for (int nt = 0; nt < 4; nt++)
            #pragma unroll
            for (int half = 0; half < 2; half++){
                size_t row = (size_t)(bm + wm*32 + mt*16 + r0 + half*8);
                int col = bn + wn*32 + nt*8 + c0;
                float v0 = c[mt][nt][half*2+0], v1 = c[mt][nt][half*2+1];
                if (act == 1){
                    v0 += R[row*ldc + col]; v1 += R[row*ldc + col + 1];
                } else if (act == 2){
                    v0 = 0.5f*v0*(1.0f + erff(v0*0.70710678118654752f));
                    v1 = 0.5f*v1*(1.0f + erff(v1*0.70710678118654752f));
                }
                *(float2*)&C[row*ldc + col] = make_float2(v0, v1);
            }
}

// ======= score + mean_value (tensor): diag-sums of S without storing S =======
// grid (4, BB*HH), 256 thr. smem: Qh/Ql 64x72, Kh/Kl 256x72 bf16, mvs[256] f32.
#define PQ 72
#define ASMEM (64*PQ*2*2 + 256*PQ*2*2 + 1024)
__global__ void __launch_bounds__(256) score_mv_tc(){
    extern __shared__ char smraw[];
    __nv_bfloat16* Qh = (__nv_bfloat16*)smraw;
    __nv_bfloat16* Ql = Qh + 64*PQ;
    __nv_bfloat16* Kh = Ql + 64*PQ;
    __nv_bfloat16* Kl = Kh + 256*PQ;
    float* mvs = (float*)(Kl + 256*PQ);
    int tid = threadIdx.x, lane = tid & 31, warp = tid >> 5;
    int bh = blockIdx.y, b = bh >> 1, h = bh & 1;
    int t0 = blockIdx.x*64;
    mvs[tid] = 0.f;
    int c2 = tid & 31, r0 = tid >> 5;
    const float* Qg = g_qkvt + (size_t)b*LL*384 + h*EE;
    const float* Kg = g_qkvt + (size_t)b*LL*384 + 128 + h*EE;
    #pragma unroll
    for (int p = 0; p < 8; p++){
        int r = p*8 + r0;
        float2 v = *(const float2*)&Qg[(size_t)(t0+r)*384 + c2*2];
        __nv_bfloat16 h0,h1,l0,l1; bfsplit(v.x,h0,l0); bfsplit(v.y,h1,l1);
        *(__nv_bfloat162*)&Qh[r*PQ + c2*2] = __nv_bfloat162(h0,h1);
        *(__nv_bfloat162*)&Ql[r*PQ + c2*2] = __nv_bfloat162(l0,l1);
    }
    #pragma unroll
    for (int p = 0; p < 32; p++){
        int r = p*8 + r0;
        float2 v = *(const float2*)&Kg[(size_t)r*384 + c2*2];
        __nv_bfloat16 h0,h1,l0,l1; bfsplit(v.x,h0,l0); bfsplit(v.y,h1,l1);
        *(__nv_bfloat162*)&Kh[r*PQ + c2*2] = __nv_bfloat162(h0,h1);
        *(__nv_bfloat162*)&Kl[r*PQ + c2*2] = __nv_bfloat162(l0,l1);
    }
    __syncthreads();
    int wm = warp & 1, wn = warp >> 1;
    int a_row = (lane & 7) + ((lane >> 3) & 1)*8, a_koff = (lane >> 4)*8;
    int b_nsel = lane >> 4, b_row = lane & 7, b_koff = ((lane >> 3) & 1)*8;
    uint32_t sQh = s2u(Qh), sQl = s2u(Ql), sKh = s2u(Kh), sKl = s2u(Kl);
    float cS[2][8][4] = {};
    #pragma unroll
    for (int kb = 0; kb < 64; kb += 16){
        uint32_t ah[2][4], al[2][4], bhf[8][2], blf[8][2];
        #pragma unroll
        for (int mt = 0; mt < 2; mt++){
            uint32_t off = (uint32_t)((wm*32 + mt*16 + a_row)*PQ + kb + a_koff)*2;
            ldm_x4(ah[mt][0],ah[mt][1],ah[mt][2],ah[mt][3], sQh + off);
            ldm_x4(al[mt][0],al[mt][1],al[mt][2],al[mt][3], sQl + off);
        }
        #pragma unroll
        for (int np = 0; np < 4; np++){
            uint32_t off = (uint32_t)((wn*64 + np*16 + b_nsel*8 + b_row)*PQ + kb + b_koff)*2;
            ldm_x4(bhf[2*np][0],bhf[2*np][1],bhf[2*np+1][0],bhf[2*np+1][1], sKh + off);
            ldm_x4(blf[2*np][0],blf[2*np][1],blf[2*np+1][0],blf[2*np+1][1], sKl + off);
        }
        #pragma unroll
        for (int mt = 0; mt < 2; mt++)
            #pragma unroll
            for (int nt = 0; nt < 8; nt++){
                mma16816(cS[mt][nt], ah[mt], bhf[nt]);
                mma16816(cS[mt][nt], ah[mt], blf[nt]);
                mma16816(cS[mt][nt], al[mt], bhf[nt]);
            }
    }
    int rb = wm*32 + (lane >> 2);
    #pragma unroll
    for (int mt = 0; mt < 2; mt++)
        #pragma unroll
        for (int nt = 0; nt < 8; nt++)
            #pragma unroll
            for (int half = 0; half < 2; half++)
                #pragma unroll
                for (int cc = 0; cc < 2; cc++){
                    int row = rb + mt*16 + half*8;
                    int col = wn*64 + nt*8 + (lane & 3)*2 + cc;
                    int tau = (t0 + row - col) & (LL-1);
                    atomicAdd(&mvs[tau], cS[mt][nt][half*2+cc]);
                }
    __syncthreads();
    atomicAdd(&g_mv[b*LL + tid], mvs[tid]*(1.0f/DD));
}

// ======= fused attention (tensor): S-tile recompute + softmax + P@Vt + combine =======
// smem plan (bytes): [0,92160) Q/K tiles (phase1), overlapped by Ssm 64x260 f32 [0,66560)
// [92160,112640) Ph/Pl/Vh/Vl 64x40 bf16 ; [112640,113664) msk ; [113664,113920) invs
#define SPIT 260
#define BSMEM (92160 + 20480 + 1024 + 256)
__global__ void __launch_bounds__(256) attn_tc(const int* __restrict__ paths){
    extern __shared__ char smraw[];
    __nv_bfloat16* Qh = (__nv_bfloat16*)smraw;
    __nv_bfloat16* Ql = Qh + 64*PQ;
    __nv_bfloat16* Kh = Ql + 64*PQ;
    __nv_bfloat16* Kl = Kh + 256*PQ;
    float* Ssm = (float*)smraw;                       // overlaps Q/K (phase 2)
    __nv_bfloat16* Ph = (__nv_bfloat16*)(smraw + 92160);
    __nv_bfloat16* Pl = Ph + 64*PIT;
    __nv_bfloat16* Vh = Pl + 64*PIT;
    __nv_bfloat16* Vl = Vh + 64*PIT;
    float* msk  = (float*)(smraw + 112640);
    float* invs = (float*)(smraw + 113664);
    int tid = threadIdx.x, lane = tid & 31, warp = tid >> 5;
    int bh = blockIdx.y, b = bh >> 1, h = bh & 1;
    int t0 = blockIdx.x*64;
    msk[tid] = (paths[b*LL + tid] < NTOT) ? 0.f : -10000.f;
    int c2 = tid & 31, r0 = tid >> 5;
    const float* Qg = g_qkvt + (size_t)b*LL*384 + h*EE;
    const float* Kg = g_qkvt + (size_t)b*LL*384 + 128 + h*EE;
    #pragma unroll
    for (int p = 0; p < 8; p++){
        int r = p*8 + r0;
        float2 v = *(const float2*)&Qg[(size_t)(t0+r)*384 + c2*2];
        __nv_bfloat16 h0,h1,l0,l1; bfsplit(v.x,h0,l0); bfsplit(v.y,h1,l1);
        *(__nv_bfloat162*)&Qh[r*PQ + c2*2] = __nv_bfloat162(h0,h1);
        *(__nv_bfloat162*)&Ql[r*PQ + c2*2] = __nv_bfloat162(l0,l1);
    }
    #pragma unroll
    for (int p = 0; p < 32; p++){
        int r = p*8 + r0;
        float2 v = *(const float2*)&Kg[(size_t)r*384 + c2*2];
        __nv_bfloat16 h0,h1,l0,l1; bfsplit(v.x,h0,l0); bfsplit(v.y,h1,l1);
        *(__nv_bfloat162*)&Kh[r*PQ + c2*2] = __nv_bfloat162(h0,h1);
        *(__nv_bfloat162*)&Kl[r*PQ + c2*2] = __nv_bfloat162(l0,l1);
    }
    __syncthreads();
    int a_row = (lane & 7) + ((lane >> 3) & 1)*8, a_koff = (lane >> 4)*8;
    int b_nsel = lane >> 4, b_row = lane & 7, b_koff = ((lane >> 3) & 1)*8;
    // ---- phase 1: S tile = Qt @ Kt^T ----
    {
        int wm = warp & 1, wn = warp >> 1;
        uint32_t sQh = s2u(Qh), sQl = s2u(Ql), sKh = s2u(Kh), sKl = s2u(Kl);
        float cS[2][8][4] = {};
        #pragma unroll
        for (int kb = 0; kb < 64; kb += 16){
            uint32_t ah[2][4], al[2][4], bhf[8][2], blf[8][2];
            #pragma unroll
            for (int mt = 0; mt < 2; mt++){
                uint32_t off = (uint32_t)((wm*32 + mt*16 + a_row)*PQ + kb + a_koff)*2;
                ldm_x4(ah[mt][0],ah[mt][1],ah[mt][2],ah[mt][3], sQh + off);
                ldm_x4(al[mt][0],al[mt][1],al[mt][2],al[mt][3], sQl + off);
            }
            #pragma unroll
            for (int np = 0; np < 4; np++){
                uint32_t off = (uint32_t)((wn*64 + np*16 + b_nsel*8 + b_row)*PQ + kb + b_koff)*2;
                ldm_x4(bhf[2*np][0],bhf[2*np][1],bhf[2*np+1][0],bhf[2*np+1][1], sKh + off);
                ldm_x4(blf[2*np][0],blf[2*np][1],blf[2*np+1][0],blf[2*np+1][1], sKl + off);
            }
            #pragma unroll
            for (int mt = 0; mt < 2; mt++)
                #pragma unroll
                for (int nt = 0; nt < 8; nt++){
                    mma16816(cS[mt][nt], ah[mt], bhf[nt]);
                    mma16816(cS[mt][nt], ah[mt], blf[nt]);
                    mma16816(cS[mt][nt], al[mt], bhf[nt]);
                }
        }
        __syncthreads();   // Q/K reads done; Ssm may overwrite
        int rb = wm*32 + (lane >> 2);
        #pragma unroll
        for (int mt = 0; mt < 2; mt++)
            #pragma unroll
            for (int nt = 0; nt < 8; nt++)
                #pragma unroll
                for (int half = 0; half < 2; half++){
                    int row = rb + mt*16 + half*8;
                    int col = wn*64 + nt*8 + (lane & 3)*2;
                    float v0 = cS[mt][nt][half*2+0]*0.125f + msk[col];
                    float v1 = cS[mt][nt][half*2+1]*0.125f + msk[col+1];
                    *(float2*)&Ssm[row*SPIT + col] = make_float2(v0, v1);
                }
    }
    __syncthreads();
    // ---- softmax rows (4 threads per row, 64-col segments) ----
    {
        int r = tid >> 2, q = tid & 3;
        float* Srow = Ssm + r*SPIT + q*64;
        float mx = -1e30f;
        #pragma unroll 16
        for (int c = 0; c < 64; c++) mx = fmaxf(mx, Srow[c]);
        mx = fmaxf(mx, __shfl_xor_sync(0xffffffffu, mx, 1));
        mx = fmaxf(mx, __shfl_xor_sync(0xffffffffu, mx, 2));
        float sum = 0.f;
        #pragma unroll 16
        for (int c = 0; c < 64; c++){
            float e = expf(Srow[c] - mx);
            Srow[c] = e;
            sum += e;
        }
        sum += __shfl_xor_sync(0xffffffffu, sum, 1);
        sum += __shfl_xor_sync(0xffffffffu, sum, 2);
        if (q == 0) invs[r] = 1.0f/sum;
    }
    // ---- phase 2: P @ Vt ----
    int wmP = warp & 3, wnP = warp >> 2;
    uint32_t sPh = s2u(Ph), sPl = s2u(Pl), sVh = s2u(Vh), sVl = s2u(Vl);
    float cP[4][4] = {};
    for (int s0 = 0; s0 < LL; s0 += 32){
        __syncthreads();
        {
            int r = tid >> 2, q = tid & 3;
            #pragma unroll
            for (int j = 0; j < 8; j++){
                int sl = q*8 + j;
                float v = Ssm[r*SPIT + s0 + sl];
                __nv_bfloat16 hi, lo; bfsplit(v, hi, lo);
                Ph[r*PIT + sl] = hi; Pl[r*PIT + sl] = lo;
            }
        }
        {
            int e = tid & 63, sj = tid >> 6;
            #pragma unroll
            for (int j = 0; j < 8; j++){
                int sl = sj*8 + j;
                float v = g_qkvt[(size_t)(b*LL + s0 + sl)*384 + 256 + h*EE + e];
                __nv_bfloat16 hi, lo; bfsplit(v, hi, lo);
                Vh[e*PIT + sl] = hi; Vl[e*PIT + sl] = lo;
            }
        }
        __syncthreads();
        #pragma unroll
        for (int ks = 0; ks < 2; ks++){
            int kb = ks*16;
            uint32_t ah[4], al[4], bhf[4][2], blf[4][2];
            uint32_t offa = (uint32_t)((wmP*16 + a_row)*PIT + kb + a_koff)*2;
            ldm_x4(ah[0],ah[1],ah[2],ah[3], sPh + offa);
            ldm_x4(al[0],al[1],al[2],al[3], sPl + offa);
            #pragma unroll
            for (int np = 0; np < 2; np++){
                uint32_t off = (uint32_t)((wnP*32 + np*16 + b_nsel*8 + b_row)*PIT + kb + b_koff)*2;
                ldm_x4(bhf[2*np][0],bhf[2*np][1],bhf[2*np+1][0],bhf[2*np+1][1], sVh + off);
                ldm_x4(blf[2*np][0],blf[2*np][1],blf[2*np+1][0],blf[2*np+1][1], sVl + off);
            }
            #pragma unroll
            for (int nt = 0; nt < 4; nt++){
                mma16816(cP[nt], ah, bhf[nt]);
                mma16816(cP[nt], ah, blf[nt]);
                mma16816(cP[nt], al, bhf[nt]);
            }
        }
    }
    // ---- epilogue: 0.9*freq + 0.1*spatial ----
    int d5[KTOP]; float w5[KTOP];
    #pragma unroll
    for (int j = 0; j < KTOP; j++){ d5[j] = g_delays[j]; w5[j] = g_w[b*KTOP + j]; }
    int rl = wmP*16 + (lane >> 2);
    #pragma unroll
    for (int nt = 0; nt < 4; nt++)
        #pragma unroll
        for (int half = 0; half < 2; half++){
            int row_l = rl + half*8;
            int t = t0 + row_l;
            float inv = invs[row_l];
            int col = wnP*32 + nt*8 + (lane & 3)*2;
            float sp0 = cP[nt][half*2+0]*inv, sp1 = cP[nt][half*2+1]*inv;
            float f0 = 0.f, f1 = 0.f;
            #pragma unroll
            for (int j = 0; j < KTOP; j++){
                int tt = (t + d5[j]) & (LL-1);
                float2 vv = *(const float2*)&g_v[(size_t)(b*LL + tt)*DD + h*EE + col];
                f0 += w5[j]*vv.x; f1 += w5[j]*vv.y;
            }
            *(float2*)&g_ao[(size_t)(b*LL + t)*DD + h*EE + col] =
                make_float2(0.9f*f0 + 0.1f*sp0, 0.9f*f1 + 0.1f*sp1);
        }
}

// ---------------- all weight transposes, one launch (both layers) ----------------
__global__ void transp_all(const float* __restrict__ Wq, const float* __restrict__ Wk,
                           const float* __restrict__ Wv, const float* __restrict__ Wp,
                           const float* __restrict__ F1, const float* __restrict__ F2){
    int j = blockIdx.x, layer = j/6, idx = j%6;
    const float* src; int K, N, doff;
    switch(idx){
        case 0: src = Wq + layer*16384; K=128; N=128; doff=0; break;
        case 1: src = Wk + layer*16384; K=128; N=128; doff=16384; break;
        case 2: src = Wv + layer*16384; K=128; N=128; doff=32768; break;
        case 3: src = Wp + layer*16384; K=128; N=128; doff=49152; break;
        case 4: src = F1 + layer*32768; K=128; N=256; doff=65536; break;
        default: src = F2 + layer*32768; K=256; N=128; doff=98304; break;
    }
    doff += layer*131072;
    int total = K*N;
    int kmask = K - 1, kshift = (K == 128) ? 7 : 8;
    for (int e = blockIdx.y*blockDim.x + threadIdx.x; e < total; e += gridDim.y*blockDim.x){
        int kk = e & kmask, n = e >> kshift;
        g_wT[doff + e] = src[(size_t)kk*N + n];
    }
}

// ---------------- embedding ----------------
__global__ void embed_k(const int* __restrict__ paths,
                        const float* __restrict__ ego,
                        const float* __restrict__ pos){
    int bt = blockIdx.x; int t = bt & (LL-1); int d = threadIdx.x;
    int p = paths[bt];
    g_x[(size_t)bt*DD + d] = ego[(size_t)p*DD + d] + pos[t*DD + d];
}

// ---------------- band-pass impulse responses (both layers) + circulant matrices ----------------
__global__ void filt2_k(){
    int layer = blockIdx.x, n = threadIdx.x;
    const int lefts[2]  = {51, 0};
    const int rights[2] = {129, 78};
    int l = lefts[layer], r = rights[layer];
    double s = 0.0;
    for (int f = l; f < r; f++){
        double w = (f == 0 || f == LL/2) ? 1.0 : 2.0;
        s += w * cos(6.283185307179586477 * (double)(f*n) / (double)LL);
    }
    g_hf[layer*LL + n] = (float)(s / (double)LL);
}
__global__ void buildC2_k(){
    int layer = blockIdx.y, t = blockIdx.x, s = threadIdx.x;
    g_C[layer*LL*LL + t*LL + s] = g_hf[layer*LL + ((t - s) & (LL-1))];
}
__global__ void zero_mv_k(){
    g_mv[blockIdx.x*1024 + threadIdx.x] = 0.f;
}

// ---------------- top-5 delays + per-batch weights ----------------
__global__ void topk_k(){
    __shared__ float sc[LL];
    int tau = threadIdx.x;
    float a = 0.f;
    for (int b = 0; b < BB; b++) a += g_mv[b*LL + tau];
    sc[tau] = a * (1.0f/BB);
    __syncthreads();
    if (tau == 0){
        for (int j = 0; j < KTOP; j++){
            float best = -1e30f; int bi = 0;
            for (int i = 0; i < LL; i++) if (sc[i] > best){ best = sc[i]; bi = i; }
            g_delays[j] = bi;
            sc[bi] = -1e30f;
        }
    }
}
__global__ void weights_k(){
    int b = threadIdx.x;
    float v[KTOP]; float mx = -1e30f;
    #pragma unroll
    for (int j = 0; j < KTOP; j++){ v[j] = g_mv[b*LL + g_delays[j]]; mx = fmaxf(mx, v[j]); }
    float s = 0.f;
    #pragma unroll
    for (int j = 0; j < KTOP; j++){ v[j] = expf(v[j]-mx); s += v[j]; }
    #pragma unroll
    for (int j = 0; j < KTOP; j++) g_w[b*KTOP + j] = v[j]/s;
}

// ---------------- final gather ----------------
__global__ void gather_k(const int* __restrict__ lengths, float* __restrict__ out){
    int b = blockIdx.x, d = threadIdx.x;
    int t = lengths[b] - 1;
    out[b*DD + d] = g_x[((size_t)b*LL + t)*DD + d];
}

// =====================================================================
extern "C" void kernel_launch(void* const* d_in, const int* in_sizes, int n_in,
                              void* d_out, int out_size){
    (void)in_sizes; (void)n_in; (void)out_size;
    const int*   paths   = (const int*)  d_in[0];
    const int*   lengths = (const int*)  d_in[1];
    const float* ego     = (const float*)d_in[4];
    const float* pos     = (const float*)d_in[5];
    const float* Wq      = (const float*)d_in[6];
    const float* Wk      = (const float*)d_in[7];
    const float* Wv      = (const float*)d_in[8];
    const float* Wp      = (const float*)d_in[9];
    const float* F1      = (const float*)d_in[10];
    const float* F2      = (const float*)d_in[11];
    float* outp = (float*)d_out;

    static bool init_done = false;
    static float *px, *pxf, *pqkvt, *pv, *pao, *pa, *ph, *pC, *pwT;
    if (!init_done){
        cudaFuncSetAttribute(score_mv_tc, cudaFuncAttributeMaxDynamicSharedMemorySize, ASMEM);
        cudaFuncSetAttribute(attn_tc,     cudaFuncAttributeMaxDynamicSharedMemorySize, BSMEM);
        cudaGetSymbolAddress((void**)&px,   g_x);
        cudaGetSymbolAddress((void**)&pxf,  g_xf);
        cudaGetSymbolAddress((void**)&pqkvt,g_qkvt);
        cudaGetSymbolAddress((void**)&pv,   g_v);
        cudaGetSymbolAddress((void**)&pao,  g_ao);
        cudaGetSymbolAddress((void**)&pa,   g_a);
        cudaGetSymbolAddress((void**)&ph,   g_h);
        cudaGetSymbolAddress((void**)&pC,   g_C);
        cudaGetSymbolAddress((void**)&pwT,  g_wT);
        init_done = true;
    }

    embed_k<<<MROWS, DD>>>(paths, ego, pos);
    filt2_k<<<2, LL>>>();
    buildC2_k<<<dim3(LL,2), LL>>>();
    transp_all<<<dim3(12,8), 256>>>(Wq, Wk, Wv, Wp, F1, F2);

    for (int k = 0; k < 2; k++){
        float* wTk = pwT + (size_t)k*131072;
        // xf = C @ x   (per batch; B = x with transposed load)
        gemm_mma<<<dim3(2,2,BB), 256>>>(pC + (size_t)k*LL*LL, LL, 0,  px, DD, (long)LL*DD, 1,
                                        pxf, DD, (long)LL*DD, nullptr, LL, 0);
        // qkvt = xf @ [Wq|Wk|Wv]
        gemm_mma<<<dim3(512,6,1), 256>>>(pxf, DD, 0,  wTk, DD, 0, 0,
                                         pqkvt, 384, 0, nullptr, DD, 0);
        // v = x @ Wv
        gemm_mma<<<dim3(512,2,1), 256>>>(px, DD, 0,  wTk + 32768, DD, 0, 0,
                                         pv, DD, 0, nullptr, DD, 0);
        zero_mv_k<<<64, 1024>>>();
        score_mv_tc<<<dim3(4, BB*HH), 256, ASMEM>>>();
        topk_k<<<1, LL>>>();
        weights_k<<<1, BB>>>();
        attn_tc<<<dim3(4, BB*HH), 256, BSMEM>>>(paths);
        // a = ao @ Wp + x
        gemm_mma<<<dim3(512,2,1), 256>>>(pao, DD, 0,  wTk + 49152, DD, 0, 0,
                                         pa, DD, 0, px, DD, 1);
        // h = gelu(a @ F1)
        gemm_mma<<<dim3(512,4,1), 256>>>(pa, DD, 0,  wTk + 65536, DD, 0, 0,
                                         ph, 2*DD, 0, nullptr, DD, 2);
        // x = h @ F2
        gemm_mma<<<dim3(512,2,1), 256>>>(ph, 2*DD, 0,  wTk + 98304, 2*DD, 0, 0,
                                         px, DD, 0, nullptr, 2*DD, 0);
    }
    gather_k<<<BB, DD>>>(lengths, outp);
}